// round 7
// baseline (speedup 1.0000x reference)
#include <cuda_runtime.h>
#include <cuda_fp16.h>
#include <mma.h>
#include <cstdint>

using namespace nvcuda;

// ---------------------------------------------------------------------------
// Problem constants
// ---------------------------------------------------------------------------
#define B_    32
#define C_    256
#define H_    56
#define W_    56
#define HW_   3136            // 56*56
#define O_    512
#define KK_   2304            // C*9
#define NPIX  100352          // B*HW

// GEMM tiling
#define BM 128
#define BN 128
#define BK 32
#define NCHUNK 72             // 2304 / 32
#define NTHREADS 256

// SMEM stage layout: A 128 rows x 80B, B 128 rows x 80B (row = 32 halfs + 8 pad)
#define A_BYTES   (128 * 80)          // 10240
#define B_BYTES   (128 * 80)          // 10240
#define STAGE_B   (A_BYTES + B_BYTES) // 20480
#define NSTAGES   5
#define SM_META   (NSTAGES * STAGE_B) // 102400
#define SMEM_TOTAL (SM_META + 1280)

// ---------------------------------------------------------------------------
// Device scratch (no runtime allocation)
// ---------------------------------------------------------------------------
__device__ __half d_Wh[O_ * KK_];     // weights fp16, [o][k'], k' = tap*256 + c
#define XPAD 16384
__device__ __half d_xt_buf[XPAD + (size_t)B_ * HW_ * C_ + XPAD]; // x^T: [b][hw][c]
__device__ int    d_mask_kind;        // 0=uint8, 1=int32, 2=float32

// ---------------------------------------------------------------------------
// Helpers
// ---------------------------------------------------------------------------
__device__ __forceinline__ uint32_t smem_to_u32(const void* p) {
    uint32_t a;
    asm("{ .reg .u64 t; cvta.to.shared.u64 t, %1; cvt.u32.u64 %0, t; }" : "=r"(a) : "l"(p));
    return a;
}

__device__ __forceinline__ void cp_async16(uint32_t dst, const void* src, int src_size) {
    asm volatile("cp.async.cg.shared.global [%0], [%1], 16, %2;"
                 :: "r"(dst), "l"(src), "r"(src_size) : "memory");
}
__device__ __forceinline__ void cp_commit() {
    asm volatile("cp.async.commit_group;" ::: "memory");
}
__device__ __forceinline__ void cp_wait3() {
    asm volatile("cp.async.wait_group 3;" ::: "memory");
}

// ---------------------------------------------------------------------------
// Mask dtype sniffing
// ---------------------------------------------------------------------------
__global__ void detect_mask_kernel(const unsigned int* __restrict__ pos) {
    __shared__ int any_big;
    __shared__ int any_f32;
    if (threadIdx.x == 0) { any_big = 0; any_f32 = 0; }
    __syncthreads();
    for (int i = threadIdx.x; i < 4096; i += 256) {
        unsigned int v = pos[i];
        if (v == 0x3F800000u) any_f32 = 1;
        else if (v > 1u)      any_big = 1;
    }
    __syncthreads();
    if (threadIdx.x == 0) d_mask_kind = any_f32 ? 2 : (any_big ? 0 : 1);
}

// ---------------------------------------------------------------------------
// Weights: masks (K,O) -> fp16 [o][k'] with k' = tap*256 + c   (k = c*9 + tap)
// ---------------------------------------------------------------------------
__global__ void prep_w_kernel(const void* __restrict__ posv,
                              const void* __restrict__ negv) {
    int i = blockIdx.x * 256 + threadIdx.x;   // over K*O
    if (i >= KK_ * O_) return;
    int k = i / O_;
    int o = i - k * O_;
    float p, n;
    int kind = d_mask_kind;
    if (kind == 1)      { p = (float)((const int*)posv)[i];   n = (float)((const int*)negv)[i]; }
    else if (kind == 2) { p = ((const float*)posv)[i];        n = ((const float*)negv)[i]; }
    else                { p = (float)((const unsigned char*)posv)[i];
                          n = (float)((const unsigned char*)negv)[i]; }
    int c = k / 9;
    int t = k - c * 9;
    d_Wh[o * KK_ + t * 256 + c] = __float2half(p - n);
}

// ---------------------------------------------------------------------------
// x (b,c,hw) fp32 -> x^T (b,hw,c) fp16, tiled SMEM transpose
// ---------------------------------------------------------------------------
__global__ void prep_xt_kernel(const float* __restrict__ x) {
    __shared__ __half tile[32][33];
    int hw0 = blockIdx.x * 32;
    int c0  = blockIdx.y * 32;
    int b   = blockIdx.z;
    int tx = threadIdx.x, ty = threadIdx.y;
    const float* xp = x + (size_t)b * C_ * HW_;
#pragma unroll
    for (int r = 0; r < 32; r += 8)
        tile[ty + r][tx] = __float2half(xp[(size_t)(c0 + ty + r) * HW_ + hw0 + tx]);
    __syncthreads();
    __half* xt = d_xt_buf + XPAD + (size_t)b * HW_ * C_;
#pragma unroll
    for (int r = 0; r < 32; r += 8)
        xt[(size_t)(hw0 + ty + r) * C_ + c0 + tx] = tile[tx][ty + r];
}

// ---------------------------------------------------------------------------
// Implicit-GEMM conv, wmma + 5-stage cp.async pipeline, 2 CTAs/SM.
// CTA: BM=128 o-channels x BN=128 pixels. 8 warps, warp grid 4(M) x 2(N),
// warp tile 32x64 -> acc[2][4] wmma 16x16x16 fragments (f16 in, f32 acc).
// K chunks: 72 x 32 (one tap x 32 contiguous channels in x^T layout).
// Loader state fully hoisted into registers; next-chunk loads issued BEFORE
// the chunk's MMAs so DMA overlaps tensor work.
// ---------------------------------------------------------------------------
__global__ __launch_bounds__(NTHREADS, 2)
void conv_gemm_kernel(float* __restrict__ out) {
    extern __shared__ __align__(1024) char smem[];
    const uint32_t smem_base = smem_to_u32(smem);
    const int tid = threadIdx.x;

    int* sXoff = (int*)(smem + SM_META);          // (b*HW + hw) * C
    int* sHW   = (int*)(smem + SM_META + 512);    // h<<16 | w
    int* sNB   = (int*)(smem + SM_META + 1024);   // per 4-pixel group: b*O*HW + hw

    const int n0 = blockIdx.x * BN;    // pixel tile
    const int m0 = blockIdx.y * BM;    // output-channel tile

    if (tid < BN) {
        int n  = n0 + tid;
        int b  = n / HW_;
        int hw = n - b * HW_;
        int h  = hw / W_;
        int w  = hw - h * W_;
        sXoff[tid] = (b * HW_ + hw) * C_;
        sHW[tid]   = (h << 16) | w;
    }
    if (tid < BN / 4) {
        int n  = n0 + 4 * tid;
        int b  = n / HW_;
        int hw = n - b * HW_;
        sNB[tid] = b * (O_ * HW_) + hw;
    }
    __syncthreads();

    // ---- hoisted loader state (per thread: 2 A tasks + 2 B tasks) ----
    // task index idx = tid + 256*r; m/j = idx>>2 (0..127), seg = idx&3
    const int idx0 = tid, idx1 = tid + NTHREADS;
    const int mj0 = idx0 >> 2, sg0 = idx0 & 3;
    const int mj1 = idx1 >> 2, sg1 = idx1 & 3;

    const __half* aSrc0 = d_Wh + (size_t)(m0 + mj0) * KK_ + sg0 * 8;
    const __half* aSrc1 = d_Wh + (size_t)(m0 + mj1) * KK_ + sg1 * 8;
    const uint32_t aOff0 = smem_base + mj0 * 80 + sg0 * 16;
    const uint32_t aOff1 = smem_base + mj1 * 80 + sg1 * 16;

    const int hw0p = sHW[mj0], hw1p = sHW[mj1];
    const int h0 = hw0p >> 16, w0 = hw0p & 0xFFFF;
    const int h1 = hw1p >> 16, w1 = hw1p & 0xFFFF;
    const __half* bSrc0 = d_xt_buf + XPAD + sXoff[mj0] + sg0 * 8;
    const __half* bSrc1 = d_xt_buf + XPAD + sXoff[mj1] + sg1 * 8;
    const uint32_t bOff0 = smem_base + A_BYTES + mj0 * 80 + sg0 * 16;
    const uint32_t bOff1 = smem_base + A_BYTES + mj1 * 80 + sg1 * 16;

    auto issue_loads = [&](int i) {
        const int s  = i % NSTAGES;
        const int t  = i >> 3;                        // tap 0..8
        const int dh = t / 3 - 1;
        const int dw = t - (t / 3) * 3 - 1;
        const int koff = i * BK;                      // == t*256 + (i&7)*32
        const int boff = (dh * W_ + dw) * C_ + (i & 7) * BK;
        const uint32_t sb = (uint32_t)(s * STAGE_B);
        cp_async16(aOff0 + sb, aSrc0 + koff, 16);
        cp_async16(aOff1 + sb, aSrc1 + koff, 16);
        int v0 = ((unsigned)(h0 + dh) < (unsigned)H_ &&
                  (unsigned)(w0 + dw) < (unsigned)W_) ? 16 : 0;
        int v1 = ((unsigned)(h1 + dh) < (unsigned)H_ &&
                  (unsigned)(w1 + dw) < (unsigned)W_) ? 16 : 0;
        cp_async16(bOff0 + sb, bSrc0 + boff, v0);
        cp_async16(bOff1 + sb, bSrc1 + boff, v1);
    };

    const int wid = tid >> 5;
    const int wm  = wid >> 1;   // 0..3 (M)
    const int wn  = wid & 1;    // 0..1 (N)

    wmma::fragment<wmma::accumulator, 16, 16, 16, float> acc[2][4];
#pragma unroll
    for (int im = 0; im < 2; ++im)
#pragma unroll
        for (int in = 0; in < 4; ++in)
            wmma::fill_fragment(acc[im][in], 0.0f);

    // ---- prologue: 4 stages in flight ----
#pragma unroll
    for (int i = 0; i < NSTAGES - 1; ++i) { issue_loads(i); cp_commit(); }

    // ---- main loop ----
    for (int i = 0; i < NCHUNK; ++i) {
        cp_wait3();
        __syncthreads();

        // issue next-chunk loads FIRST so DMA overlaps this chunk's MMAs
        if (i + NSTAGES - 1 < NCHUNK) issue_loads(i + NSTAGES - 1);
        cp_commit();   // unconditional: keeps wait_group accounting exact

        const int s = i % NSTAGES;
        const __half* as = (const __half*)(smem + s * STAGE_B);
        const __half* bs = (const __half*)(smem + s * STAGE_B + A_BYTES);
#pragma unroll
        for (int kk = 0; kk < BK; kk += 16) {
            wmma::fragment<wmma::matrix_a, 16, 16, 16, __half, wmma::row_major> af[2];
            wmma::fragment<wmma::matrix_b, 16, 16, 16, __half, wmma::col_major> bf[4];
#pragma unroll
            for (int im = 0; im < 2; ++im)
                wmma::load_matrix_sync(af[im], as + (wm * 32 + im * 16) * 40 + kk, 40);
#pragma unroll
            for (int in = 0; in < 4; ++in)
                wmma::load_matrix_sync(bf[in], bs + (wn * 64 + in * 16) * 40 + kk, 40);
#pragma unroll
            for (int im = 0; im < 2; ++im)
#pragma unroll
                for (int in = 0; in < 4; ++in)
                    wmma::mma_sync(acc[im][in], af[im], bf[in], acc[im][in]);
        }
    }
    __syncthreads();

    // ---- epilogue: 4 passes of 32 M-rows through SMEM, float4 scatter ----
    float* Cs = (float*)smem;   // [32][132]
#pragma unroll 1
    for (int pass = 0; pass < 4; ++pass) {
        if (wm == pass) {
#pragma unroll
            for (int im = 0; im < 2; ++im)
#pragma unroll
                for (int in = 0; in < 4; ++in)
                    wmma::store_matrix_sync(Cs + (im * 16) * 132 + wn * 64 + in * 16,
                                            acc[im][in], 132, wmma::mem_row_major);
        }
        __syncthreads();
#pragma unroll
        for (int r = 0; r < 4; ++r) {
            int e = tid + NTHREADS * r;       // 1024 float4 tasks
            int m = e >> 5;                   // 0..31 row
            int q = e & 31;                   // 4-pixel group
            float4 v = *(const float4*)(Cs + m * 132 + q * 4);
            *(float4*)(out + sNB[q] + (size_t)(m0 + pass * 32 + m) * HW_) = v;
        }
        __syncthreads();
    }
}

// ---------------------------------------------------------------------------
// Launch
// ---------------------------------------------------------------------------
extern "C" void kernel_launch(void* const* d_in, const int* in_sizes, int n_in,
                              void* d_out, int out_size) {
    const float* x   = (const float*)d_in[0];
    const void*  pos = d_in[1];
    const void*  neg = d_in[2];
    float* out = (float*)d_out;

    static bool attr_set = false;
    if (!attr_set) {
        cudaFuncSetAttribute(conv_gemm_kernel,
                             cudaFuncAttributeMaxDynamicSharedMemorySize, SMEM_TOTAL);
        attr_set = true;
    }

    // 0) sniff mask representation
    detect_mask_kernel<<<1, 256>>>((const unsigned int*)pos);
    // 1) weights -> fp16 [o][k'] (tap-major K permutation)
    prep_w_kernel<<<(KK_ * O_ + 255) / 256, 256>>>(pos, neg);
    // 2) x -> fp16 transposed [b][hw][c]
    dim3 tgrid(HW_ / 32, C_ / 32, B_);
    prep_xt_kernel<<<tgrid, dim3(32, 8)>>>(x);
    // 3) wmma implicit GEMM: grid = (784 pixel tiles, 4 m tiles), 2 CTAs/SM
    dim3 grid(NPIX / BN, O_ / BM);
    conv_gemm_kernel<<<grid, NTHREADS, SMEM_TOTAL>>>(out);
}

// round 9
// speedup vs baseline: 1.1113x; 1.1113x over previous
#include <cuda_runtime.h>
#include <cuda_fp16.h>
#include <mma.h>
#include <cstdint>

using namespace nvcuda;

// ---------------------------------------------------------------------------
// Problem constants
// ---------------------------------------------------------------------------
#define B_    32
#define C_    256
#define H_    56
#define W_    56
#define HW_   3136            // 56*56
#define O_    512
#define KK_   2304            // C*9
#define NPIX  100352          // B*HW

// GEMM tiling
#define BM 128
#define BN 128
#define BK 64
#define NCHUNK 36             // 2304 / 64
#define NTHREADS 256

// SMEM stage layout: A 128 rows x 144B, B 128 rows x 144B (row = 64 halfs + 8 pad)
#define ROW_B     144
#define A_BYTES   (128 * ROW_B)       // 18432
#define B_BYTES   (128 * ROW_B)       // 18432
#define STAGE_B   (A_BYTES + B_BYTES) // 36864
#define NSTAGES   3
#define SM_META   (NSTAGES * STAGE_B) // 110592
#define SMEM_TOTAL (SM_META + 1280)   // 111872  (2 CTAs/SM: 2x <= 227KB)

// ---------------------------------------------------------------------------
// Device scratch (no runtime allocation)
// ---------------------------------------------------------------------------
__device__ __half d_Wh[O_ * KK_];     // weights fp16, [o][k'], k' = tap*256 + c
#define XPAD 16384
__device__ __half d_xt_buf[XPAD + (size_t)B_ * HW_ * C_ + XPAD]; // x^T: [b][hw][c]
__device__ int    d_mask_kind;        // 0=uint8, 1=int32, 2=float32

// ---------------------------------------------------------------------------
// Helpers
// ---------------------------------------------------------------------------
__device__ __forceinline__ uint32_t smem_to_u32(const void* p) {
    uint32_t a;
    asm("{ .reg .u64 t; cvta.to.shared.u64 t, %1; cvt.u32.u64 %0, t; }" : "=r"(a) : "l"(p));
    return a;
}

__device__ __forceinline__ void cp_async16(uint32_t dst, const void* src, int src_size) {
    asm volatile("cp.async.cg.shared.global [%0], [%1], 16, %2;"
                 :: "r"(dst), "l"(src), "r"(src_size) : "memory");
}
__device__ __forceinline__ void cp_commit() {
    asm volatile("cp.async.commit_group;" ::: "memory");
}
__device__ __forceinline__ void cp_wait1() {
    asm volatile("cp.async.wait_group 1;" ::: "memory");
}

// ---------------------------------------------------------------------------
// Mask dtype sniffing
// ---------------------------------------------------------------------------
__global__ void detect_mask_kernel(const unsigned int* __restrict__ pos) {
    __shared__ int any_big;
    __shared__ int any_f32;
    if (threadIdx.x == 0) { any_big = 0; any_f32 = 0; }
    __syncthreads();
    for (int i = threadIdx.x; i < 4096; i += 256) {
        unsigned int v = pos[i];
        if (v == 0x3F800000u) any_f32 = 1;
        else if (v > 1u)      any_big = 1;
    }
    __syncthreads();
    if (threadIdx.x == 0) d_mask_kind = any_f32 ? 2 : (any_big ? 0 : 1);
}

// ---------------------------------------------------------------------------
// Weights: masks (K,O) -> fp16 [o][k'] with k' = tap*256 + c   (k = c*9 + tap)
// ---------------------------------------------------------------------------
__global__ void prep_w_kernel(const void* __restrict__ posv,
                              const void* __restrict__ negv) {
    int i = blockIdx.x * 256 + threadIdx.x;   // over K*O
    if (i >= KK_ * O_) return;
    int k = i / O_;
    int o = i - k * O_;
    float p, n;
    int kind = d_mask_kind;
    if (kind == 1)      { p = (float)((const int*)posv)[i];   n = (float)((const int*)negv)[i]; }
    else if (kind == 2) { p = ((const float*)posv)[i];        n = ((const float*)negv)[i]; }
    else                { p = (float)((const unsigned char*)posv)[i];
                          n = (float)((const unsigned char*)negv)[i]; }
    int c = k / 9;
    int t = k - c * 9;
    d_Wh[o * KK_ + t * 256 + c] = __float2half(p - n);
}

// ---------------------------------------------------------------------------
// x (b,c,hw) fp32 -> x^T (b,hw,c) fp16, tiled SMEM transpose
// ---------------------------------------------------------------------------
__global__ void prep_xt_kernel(const float* __restrict__ x) {
    __shared__ __half tile[32][33];
    int hw0 = blockIdx.x * 32;
    int c0  = blockIdx.y * 32;
    int b   = blockIdx.z;
    int tx = threadIdx.x, ty = threadIdx.y;
    const float* xp = x + (size_t)b * C_ * HW_;
#pragma unroll
    for (int r = 0; r < 32; r += 8)
        tile[ty + r][tx] = __float2half(xp[(size_t)(c0 + ty + r) * HW_ + hw0 + tx]);
    __syncthreads();
    __half* xt = d_xt_buf + XPAD + (size_t)b * HW_ * C_;
#pragma unroll
    for (int r = 0; r < 32; r += 8)
        xt[(size_t)(hw0 + ty + r) * C_ + c0 + tx] = tile[tx][ty + r];
}

// ---------------------------------------------------------------------------
// Implicit-GEMM conv, wmma + 3-stage cp.async pipeline (BK=64), 2 CTAs/SM.
// CTA: BM=128 o-channels x BN=128 pixels. 8 warps, warp grid 4(M) x 2(N),
// warp tile 32x64 -> acc[2][4] wmma 16x16x16 fragments (f16 in, f32 acc).
// K chunks: 36 x 64 (one tap x 64 contiguous channels in x^T layout) --
// half the barrier/wait bubbles of the BK=32 version.
// ---------------------------------------------------------------------------
__global__ __launch_bounds__(NTHREADS, 2)
void conv_gemm_kernel(float* __restrict__ out) {
    extern __shared__ __align__(1024) char smem[];
    const uint32_t smem_base = smem_to_u32(smem);
    const int tid = threadIdx.x;

    int* sXoff = (int*)(smem + SM_META);          // (b*HW + hw) * C
    int* sHW   = (int*)(smem + SM_META + 512);    // h<<16 | w
    int* sNB   = (int*)(smem + SM_META + 1024);   // per 4-pixel group: b*O*HW + hw

    const int n0 = blockIdx.x * BN;    // pixel tile
    const int m0 = blockIdx.y * BM;    // output-channel tile

    if (tid < BN) {
        int n  = n0 + tid;
        int b  = n / HW_;
        int hw = n - b * HW_;
        int h  = hw / W_;
        int w  = hw - h * W_;
        sXoff[tid] = (b * HW_ + hw) * C_;
        sHW[tid]   = (h << 16) | w;
    }
    if (tid < BN / 4) {
        int n  = n0 + 4 * tid;
        int b  = n / HW_;
        int hw = n - b * HW_;
        sNB[tid] = b * (O_ * HW_) + hw;
    }
    __syncthreads();

    // ---- stage loader: chunk i -> stage i % NSTAGES ----
    auto issue_loads = [&](int i) {
        const int s  = i % NSTAGES;
        const int t  = i >> 2;              // tap 0..8  (4 chunks per tap)
        const int c0 = (i & 3) * BK;        // channel offset 0/64/128/192
        const int dh = t / 3 - 1;
        const int dw = t - (t / 3) * 3 - 1;
        // A: 1024 tasks of 16B (128 rows x 8 segs); four per thread
#pragma unroll
        for (int r = 0; r < 4; ++r) {
            int idx = tid + NTHREADS * r;
            int m   = idx >> 3;
            int seg = idx & 7;
            uint32_t dst = smem_base + s * STAGE_B + m * ROW_B + seg * 16;
            const __half* src = d_Wh + (size_t)(m0 + m) * KK_ + t * 256 + c0 + seg * 8;
            cp_async16(dst, src, 16);
        }
        // B: 1024 tasks of 16B (128 pixel-rows x 8 segs); four per thread
        const int tapd = (dh * W_ + dw) * C_;
#pragma unroll
        for (int r = 0; r < 4; ++r) {
            int idx = tid + NTHREADS * r;
            int j   = idx >> 3;
            int seg = idx & 7;
            int hwp = sHW[j];
            int h = hwp >> 16, w = hwp & 0xFFFF;
            int valid = ((unsigned)(h + dh) < (unsigned)H_ &&
                         (unsigned)(w + dw) < (unsigned)W_) ? 16 : 0;
            uint32_t dst = smem_base + s * STAGE_B + A_BYTES + j * ROW_B + seg * 16;
            const __half* src = d_xt_buf + XPAD + sXoff[j] + tapd + c0 + seg * 8;
            cp_async16(dst, src, valid);
        }
    };

    const int wid = tid >> 5;
    const int wm  = wid >> 1;   // 0..3 (M)
    const int wn  = wid & 1;    // 0..1 (N)

    wmma::fragment<wmma::accumulator, 16, 16, 16, float> acc[2][4];
#pragma unroll
    for (int im = 0; im < 2; ++im)
#pragma unroll
        for (int in = 0; in < 4; ++in)
            wmma::fill_fragment(acc[im][in], 0.0f);

    // ---- prologue: 2 stages in flight ----
#pragma unroll
    for (int i = 0; i < NSTAGES - 1; ++i) { issue_loads(i); cp_commit(); }

    // ---- main loop ----
    for (int i = 0; i < NCHUNK; ++i) {
        cp_wait1();
        __syncthreads();

        const int s = i % NSTAGES;
        const __half* as = (const __half*)(smem + s * STAGE_B);
        const __half* bs = (const __half*)(smem + s * STAGE_B + A_BYTES);
#pragma unroll
        for (int kk = 0; kk < BK; kk += 16) {
            wmma::fragment<wmma::matrix_a, 16, 16, 16, __half, wmma::row_major> af[2];
            wmma::fragment<wmma::matrix_b, 16, 16, 16, __half, wmma::col_major> bf[4];
#pragma unroll
            for (int im = 0; im < 2; ++im)
                wmma::load_matrix_sync(af[im], as + (wm * 32 + im * 16) * 72 + kk, 72);
#pragma unroll
            for (int in = 0; in < 4; ++in)
                wmma::load_matrix_sync(bf[in], bs + (wn * 64 + in * 16) * 72 + kk, 72);
#pragma unroll
            for (int im = 0; im < 2; ++im)
#pragma unroll
                for (int in = 0; in < 4; ++in)
                    wmma::mma_sync(acc[im][in], af[im], bf[in], acc[im][in]);
        }

        if (i + NSTAGES - 1 < NCHUNK) issue_loads(i + NSTAGES - 1);
        cp_commit();   // unconditional: keeps wait_group accounting exact
    }
    __syncthreads();

    // ---- epilogue: 4 passes of 32 M-rows through SMEM, float4 scatter ----
    float* Cs = (float*)smem;   // [32][132]
#pragma unroll 1
    for (int pass = 0; pass < 4; ++pass) {
        if (wm == pass) {
#pragma unroll
            for (int im = 0; im < 2; ++im)
#pragma unroll
                for (int in = 0; in < 4; ++in)
                    wmma::store_matrix_sync(Cs + (im * 16) * 132 + wn * 64 + in * 16,
                                            acc[im][in], 132, wmma::mem_row_major);
        }
        __syncthreads();
#pragma unroll
        for (int r = 0; r < 4; ++r) {
            int e = tid + NTHREADS * r;       // 1024 float4 tasks
            int m = e >> 5;                   // 0..31 row
            int q = e & 31;                   // 4-pixel group
            float4 v = *(const float4*)(Cs + m * 132 + q * 4);
            *(float4*)(out + sNB[q] + (size_t)(m0 + pass * 32 + m) * HW_) = v;
        }
        __syncthreads();
    }
}

// ---------------------------------------------------------------------------
// Launch
// ---------------------------------------------------------------------------
extern "C" void kernel_launch(void* const* d_in, const int* in_sizes, int n_in,
                              void* d_out, int out_size) {
    const float* x   = (const float*)d_in[0];
    const void*  pos = d_in[1];
    const void*  neg = d_in[2];
    float* out = (float*)d_out;

    static bool attr_set = false;
    if (!attr_set) {
        cudaFuncSetAttribute(conv_gemm_kernel,
                             cudaFuncAttributeMaxDynamicSharedMemorySize, SMEM_TOTAL);
        attr_set = true;
    }

    // 0) sniff mask representation
    detect_mask_kernel<<<1, 256>>>((const unsigned int*)pos);
    // 1) weights -> fp16 [o][k'] (tap-major K permutation)
    prep_w_kernel<<<(KK_ * O_ + 255) / 256, 256>>>(pos, neg);
    // 2) x -> fp16 transposed [b][hw][c]
    dim3 tgrid(HW_ / 32, C_ / 32, B_);
    prep_xt_kernel<<<tgrid, dim3(32, 8)>>>(x);
    // 3) wmma implicit GEMM: grid = (784 pixel tiles, 4 m tiles), 2 CTAs/SM
    dim3 grid(NPIX / BN, O_ / BM);
    conv_gemm_kernel<<<grid, NTHREADS, SMEM_TOTAL>>>(out);
}

// round 10
// speedup vs baseline: 1.1868x; 1.0679x over previous
#include <cuda_runtime.h>
#include <cuda_fp16.h>
#include <mma.h>
#include <cstdint>

using namespace nvcuda;

// ---------------------------------------------------------------------------
// Problem constants
// ---------------------------------------------------------------------------
#define B_    32
#define C_    256
#define H_    56
#define W_    56
#define HW_   3136            // 56*56
#define O_    512
#define KK_   2304            // C*9
#define NPIX  100352          // B*HW

// GEMM tiling
#define BM 128
#define BN 128
#define BK 64
#define NCHUNK 36             // 2304 / 64
#define NTHREADS 256

// SMEM stage layout: A 128 rows x 144B, B 128 rows x 144B (row = 64 halfs + 8 pad)
#define ROW_B     144
#define A_BYTES   (128 * ROW_B)       // 18432
#define B_BYTES   (128 * ROW_B)       // 18432
#define STAGE_B   (A_BYTES + B_BYTES) // 36864
#define NSTAGES   3
#define SM_META   (NSTAGES * STAGE_B) // 110592
#define SMEM_TOTAL (SM_META + 1280)   // 111872  (2 CTAs/SM: 2x <= 227KB)

// ---------------------------------------------------------------------------
// Device scratch (no runtime allocation)
// ---------------------------------------------------------------------------
__device__ __half d_Wh[O_ * KK_];     // weights fp16, [o][k'], k' = tap*256 + c
#define XPAD 16384
__device__ __half d_xt_buf[XPAD + (size_t)B_ * HW_ * C_ + XPAD]; // x^T: [b][hw][c]
__device__ int    d_mask_kind;        // 0=uint8, 1=int32, 2=float32

// ---------------------------------------------------------------------------
// Helpers
// ---------------------------------------------------------------------------
__device__ __forceinline__ uint32_t smem_to_u32(const void* p) {
    uint32_t a;
    asm("{ .reg .u64 t; cvta.to.shared.u64 t, %1; cvt.u32.u64 %0, t; }" : "=r"(a) : "l"(p));
    return a;
}

__device__ __forceinline__ void cp_async16(uint32_t dst, const void* src, int src_size) {
    asm volatile("cp.async.cg.shared.global [%0], [%1], 16, %2;"
                 :: "r"(dst), "l"(src), "r"(src_size) : "memory");
}
__device__ __forceinline__ void cp_commit() {
    asm volatile("cp.async.commit_group;" ::: "memory");
}
__device__ __forceinline__ void cp_wait1() {
    asm volatile("cp.async.wait_group 1;" ::: "memory");
}

// ---------------------------------------------------------------------------
// Mask dtype sniffing
// ---------------------------------------------------------------------------
__global__ void detect_mask_kernel(const unsigned int* __restrict__ pos) {
    __shared__ int any_big;
    __shared__ int any_f32;
    if (threadIdx.x == 0) { any_big = 0; any_f32 = 0; }
    __syncthreads();
    for (int i = threadIdx.x; i < 4096; i += 256) {
        unsigned int v = pos[i];
        if (v == 0x3F800000u) any_f32 = 1;
        else if (v > 1u)      any_big = 1;
    }
    __syncthreads();
    if (threadIdx.x == 0) d_mask_kind = any_f32 ? 2 : (any_big ? 0 : 1);
}

// ---------------------------------------------------------------------------
// Weights: masks (K,O) -> fp16 [o][k'] with k' = tap*256 + c   (k = c*9 + tap)
// ---------------------------------------------------------------------------
__global__ void prep_w_kernel(const void* __restrict__ posv,
                              const void* __restrict__ negv) {
    int i = blockIdx.x * 256 + threadIdx.x;   // over K*O
    if (i >= KK_ * O_) return;
    int k = i / O_;
    int o = i - k * O_;
    float p, n;
    int kind = d_mask_kind;
    if (kind == 1)      { p = (float)((const int*)posv)[i];   n = (float)((const int*)negv)[i]; }
    else if (kind == 2) { p = ((const float*)posv)[i];        n = ((const float*)negv)[i]; }
    else                { p = (float)((const unsigned char*)posv)[i];
                          n = (float)((const unsigned char*)negv)[i]; }
    int c = k / 9;
    int t = k - c * 9;
    d_Wh[o * KK_ + t * 256 + c] = __float2half(p - n);
}

// ---------------------------------------------------------------------------
// x (b,c,hw) fp32 -> x^T (b,hw,c) fp16, tiled SMEM transpose
// ---------------------------------------------------------------------------
__global__ void prep_xt_kernel(const float* __restrict__ x) {
    __shared__ __half tile[32][33];
    int hw0 = blockIdx.x * 32;
    int c0  = blockIdx.y * 32;
    int b   = blockIdx.z;
    int tx = threadIdx.x, ty = threadIdx.y;
    const float* xp = x + (size_t)b * C_ * HW_;
#pragma unroll
    for (int r = 0; r < 32; r += 8)
        tile[ty + r][tx] = __float2half(xp[(size_t)(c0 + ty + r) * HW_ + hw0 + tx]);
    __syncthreads();
    __half* xt = d_xt_buf + XPAD + (size_t)b * HW_ * C_;
#pragma unroll
    for (int r = 0; r < 32; r += 8)
        xt[(size_t)(hw0 + ty + r) * C_ + c0 + tx] = tile[tx][ty + r];
}

// ---------------------------------------------------------------------------
// Implicit-GEMM conv, wmma + 3-stage cp.async pipeline (BK=64), 2 CTAs/SM.
// CTA: BM=128 o-channels x BN=128 pixels. 8 warps, warp grid 4(M) x 2(N),
// warp tile 32x64 -> acc[2][4] wmma 16x16x16 fragments (f16 in, f32 acc).
// K chunks: 36 x 64 (one tap x 64 contiguous channels in x^T layout).
// Loader state hoisted to registers (base pointers + 9-bit tap validity
// masks); load issue stays AFTER the MMA block (known-good R9 order).
// ---------------------------------------------------------------------------
__global__ __launch_bounds__(NTHREADS, 2)
void conv_gemm_kernel(float* __restrict__ out) {
    extern __shared__ __align__(1024) char smem[];
    const uint32_t smem_base = smem_to_u32(smem);
    const int tid = threadIdx.x;

    int* sXoff = (int*)(smem + SM_META);          // (b*HW + hw) * C
    int* sHW   = (int*)(smem + SM_META + 512);    // h<<16 | w
    int* sNB   = (int*)(smem + SM_META + 1024);   // per 4-pixel group: b*O*HW + hw

    const int n0 = blockIdx.x * BN;    // pixel tile
    const int m0 = blockIdx.y * BM;    // output-channel tile

    if (tid < BN) {
        int n  = n0 + tid;
        int b  = n / HW_;
        int hw = n - b * HW_;
        int h  = hw / W_;
        int w  = hw - h * W_;
        sXoff[tid] = (b * HW_ + hw) * C_;
        sHW[tid]   = (h << 16) | w;
    }
    if (tid < BN / 4) {
        int n  = n0 + 4 * tid;
        int b  = n / HW_;
        int hw = n - b * HW_;
        sNB[tid] = b * (O_ * HW_) + hw;
    }
    __syncthreads();

    // ---- hoisted loader state ----
    // task idx = tid + 256*r: seg = idx&7 == tid&7 (constant), m/j = (tid>>3)+32r
    const int sg      = tid & 7;
    const int mj_base = tid >> 3;

    const __half*  aSrcBase = d_Wh + (size_t)(m0 + mj_base) * KK_ + sg * 8;
    const uint32_t aOffBase = smem_base + mj_base * ROW_B + sg * 16;

    const __half* bSrc[4];
    uint32_t      bOff[4];
    uint32_t      vmask[4];   // bit t set => tap t in-bounds for this pixel
#pragma unroll
    for (int r = 0; r < 4; ++r) {
        int j   = mj_base + 32 * r;
        int hwp = sHW[j];
        int h = hwp >> 16, w = hwp & 0xFFFF;
        uint32_t msk = 0;
#pragma unroll
        for (int t = 0; t < 9; ++t) {
            int dh = t / 3 - 1;
            int dw = t - (t / 3) * 3 - 1;
            if ((unsigned)(h + dh) < (unsigned)H_ && (unsigned)(w + dw) < (unsigned)W_)
                msk |= 1u << t;
        }
        vmask[r] = msk;
        bSrc[r]  = d_xt_buf + XPAD + sXoff[j] + sg * 8;
        bOff[r]  = smem_base + A_BYTES + j * ROW_B + sg * 16;
    }

    // ---- stage loader: chunk i -> stage i % NSTAGES ----
    auto issue_loads = [&](int i) {
        const int s    = i % NSTAGES;
        const int t    = i >> 2;                  // tap 0..8 (4 chunks per tap)
        const int dh   = t / 3 - 1;
        const int dw   = t - (t / 3) * 3 - 1;
        const int koff = i * BK;                  // == t*256 + (i&3)*64
        const int boff = (dh * W_ + dw) * C_ + (i & 3) * BK;
        const uint32_t sb = (uint32_t)(s * STAGE_B);
#pragma unroll
        for (int r = 0; r < 4; ++r)
            cp_async16(aOffBase + sb + r * (32 * ROW_B),
                       aSrcBase + koff + (size_t)r * (32 * KK_), 16);
#pragma unroll
        for (int r = 0; r < 4; ++r)
            cp_async16(bOff[r] + sb, bSrc[r] + boff,
                       ((vmask[r] >> t) & 1u) ? 16 : 0);
    };

    const int wid = tid >> 5;
    const int wm  = wid >> 1;   // 0..3 (M)
    const int wn  = wid & 1;    // 0..1 (N)

    wmma::fragment<wmma::accumulator, 16, 16, 16, float> acc[2][4];
#pragma unroll
    for (int im = 0; im < 2; ++im)
#pragma unroll
        for (int in = 0; in < 4; ++in)
            wmma::fill_fragment(acc[im][in], 0.0f);

    // ---- prologue: 2 stages in flight ----
#pragma unroll
    for (int i = 0; i < NSTAGES - 1; ++i) { issue_loads(i); cp_commit(); }

    // ---- main loop ----
    for (int i = 0; i < NCHUNK; ++i) {
        cp_wait1();
        __syncthreads();

        const int s = i % NSTAGES;
        const __half* as = (const __half*)(smem + s * STAGE_B);
        const __half* bs = (const __half*)(smem + s * STAGE_B + A_BYTES);
#pragma unroll
        for (int kk = 0; kk < BK; kk += 16) {
            wmma::fragment<wmma::matrix_a, 16, 16, 16, __half, wmma::row_major> af[2];
            wmma::fragment<wmma::matrix_b, 16, 16, 16, __half, wmma::col_major> bf[4];
#pragma unroll
            for (int im = 0; im < 2; ++im)
                wmma::load_matrix_sync(af[im], as + (wm * 32 + im * 16) * 72 + kk, 72);
#pragma unroll
            for (int in = 0; in < 4; ++in)
                wmma::load_matrix_sync(bf[in], bs + (wn * 64 + in * 16) * 72 + kk, 72);
#pragma unroll
            for (int im = 0; im < 2; ++im)
#pragma unroll
                for (int in = 0; in < 4; ++in)
                    wmma::mma_sync(acc[im][in], af[im], bf[in], acc[im][in]);
        }

        if (i + NSTAGES - 1 < NCHUNK) issue_loads(i + NSTAGES - 1);
        cp_commit();   // unconditional: keeps wait_group accounting exact
    }
    __syncthreads();

    // ---- epilogue: 4 passes of 32 M-rows through SMEM, float4 scatter ----
    float* Cs = (float*)smem;   // [32][132]
#pragma unroll 1
    for (int pass = 0; pass < 4; ++pass) {
        if (wm == pass) {
#pragma unroll
            for (int im = 0; im < 2; ++im)
#pragma unroll
                for (int in = 0; in < 4; ++in)
                    wmma::store_matrix_sync(Cs + (im * 16) * 132 + wn * 64 + in * 16,
                                            acc[im][in], 132, wmma::mem_row_major);
        }
        __syncthreads();
#pragma unroll
        for (int r = 0; r < 4; ++r) {
            int e = tid + NTHREADS * r;       // 1024 float4 tasks
            int m = e >> 5;                   // 0..31 row
            int q = e & 31;                   // 4-pixel group
            float4 v = *(const float4*)(Cs + m * 132 + q * 4);
            *(float4*)(out + sNB[q] + (size_t)(m0 + pass * 32 + m) * HW_) = v;
        }
        __syncthreads();
    }
}

// ---------------------------------------------------------------------------
// Launch
// ---------------------------------------------------------------------------
extern "C" void kernel_launch(void* const* d_in, const int* in_sizes, int n_in,
                              void* d_out, int out_size) {
    const float* x   = (const float*)d_in[0];
    const void*  pos = d_in[1];
    const void*  neg = d_in[2];
    float* out = (float*)d_out;

    static bool attr_set = false;
    if (!attr_set) {
        cudaFuncSetAttribute(conv_gemm_kernel,
                             cudaFuncAttributeMaxDynamicSharedMemorySize, SMEM_TOTAL);
        attr_set = true;
    }

    // 0) sniff mask representation
    detect_mask_kernel<<<1, 256>>>((const unsigned int*)pos);
    // 1) weights -> fp16 [o][k'] (tap-major K permutation)
    prep_w_kernel<<<(KK_ * O_ + 255) / 256, 256>>>(pos, neg);
    // 2) x -> fp16 transposed [b][hw][c]
    dim3 tgrid(HW_ / 32, C_ / 32, B_);
    prep_xt_kernel<<<tgrid, dim3(32, 8)>>>(x);
    // 3) wmma implicit GEMM: grid = (784 pixel tiles, 4 m tiles), 2 CTAs/SM
    dim3 grid(NPIX / BN, O_ / BM);
    conv_gemm_kernel<<<grid, NTHREADS, SMEM_TOTAL>>>(out);
}